// round 1
// baseline (speedup 1.0000x reference)
#include <cuda_runtime.h>

#define FOUT 64
#define KTOT 256
#define NMAX 100000
#define EMAX 3200000
#define TROWS 128
#define KC 32

// ---------------- scratch (device globals: allowed; no runtime allocs) ----------------
__device__ __align__(256) float g_h[NMAX * FOUT];          // 25.6 MB: h = xW
__device__ __align__(256) float g_e[EMAX + NMAX];          // 13.2 MB: per-edge logits
__device__ float g_asrc[NMAX];
__device__ float g_adst[NMAX];
__device__ float g_max[NMAX];
__device__ float g_denom[NMAX];

__device__ __forceinline__ void atomicMaxFloat(float* addr, float val) {
    // standard ordered-int trick; init value is -inf so every node (self-loop) updates
    if (val >= 0.f) atomicMax((int*)addr, __float_as_int(val));
    else            atomicMin((unsigned int*)addr, __float_as_uint(val));
}

// ---------------- kernel 1: init ----------------
__global__ void init_kernel(float4* __restrict__ out4, int n) {
    int i = blockIdx.x * blockDim.x + threadIdx.x;
    if (i < n * (FOUT / 4)) out4[i] = make_float4(0.f, 0.f, 0.f, 0.f);
    if (i < n) {
        g_denom[i] = 0.f;
        g_max[i]   = __int_as_float(0xff800000);  // -inf
    }
}

// ---------------- kernel 2: h = x @ W, plus a_src/a_dst epilogue ----------------
// 256 threads, tile 128 rows x 64 cols. Thread (ty,tx): ty=tid>>3 (4 rows), tx=tid&7 (8 cols).
__global__ __launch_bounds__(256) void gemm_kernel(
    const float* __restrict__ x, const float* __restrict__ W,
    const float* __restrict__ att_src, const float* __restrict__ att_dst, int n)
{
    __shared__ float xs[TROWS][KC + 1];   // +1 pad: conflict-free scalar reads/writes
    __shared__ float ws[KC][FOUT];

    int tid = threadIdx.x;
    int tx = tid & 7;
    int ty = tid >> 3;
    int row0 = blockIdx.x * TROWS;

    float acc[4][8];
#pragma unroll
    for (int r = 0; r < 4; r++)
#pragma unroll
        for (int c = 0; c < 8; c++) acc[r][c] = 0.f;

    for (int k0 = 0; k0 < KTOT; k0 += KC) {
        // load W chunk [KC][64]
#pragma unroll
        for (int i = 0; i < 2; i++) {
            int kk = (tid >> 4) + i * 16;
            int cc = (tid & 15) * 4;
            *reinterpret_cast<float4*>(&ws[kk][cc]) =
                *reinterpret_cast<const float4*>(&W[(k0 + kk) * FOUT + cc]);
        }
        // load x chunk [128][KC]
        {
            int lr = tid >> 3;
            int kq = (tid & 7) * 4;
#pragma unroll
            for (int i = 0; i < 4; i++) {
                int row = row0 + lr + i * 32;
                float4 v = make_float4(0.f, 0.f, 0.f, 0.f);
                if (row < n)
                    v = *reinterpret_cast<const float4*>(&x[row * KTOT + k0 + kq]);
                xs[lr + i * 32][kq + 0] = v.x;
                xs[lr + i * 32][kq + 1] = v.y;
                xs[lr + i * 32][kq + 2] = v.z;
                xs[lr + i * 32][kq + 3] = v.w;
            }
        }
        __syncthreads();
#pragma unroll
        for (int k = 0; k < KC; k++) {
            float4 w0 = *reinterpret_cast<const float4*>(&ws[k][tx * 8]);
            float4 w1 = *reinterpret_cast<const float4*>(&ws[k][tx * 8 + 4]);
#pragma unroll
            for (int r = 0; r < 4; r++) {
                float xv = xs[ty * 4 + r][k];
                acc[r][0] += xv * w0.x; acc[r][1] += xv * w0.y;
                acc[r][2] += xv * w0.z; acc[r][3] += xv * w0.w;
                acc[r][4] += xv * w1.x; acc[r][5] += xv * w1.y;
                acc[r][6] += xv * w1.z; acc[r][7] += xv * w1.w;
            }
        }
        __syncthreads();
    }

    // epilogue: store h, compute per-row attention halves (reduce across tx lanes)
    float4 as0 = *reinterpret_cast<const float4*>(&att_src[tx * 8]);
    float4 as1 = *reinterpret_cast<const float4*>(&att_src[tx * 8 + 4]);
    float4 ad0 = *reinterpret_cast<const float4*>(&att_dst[tx * 8]);
    float4 ad1 = *reinterpret_cast<const float4*>(&att_dst[tx * 8 + 4]);

#pragma unroll
    for (int r = 0; r < 4; r++) {
        int row = row0 + ty * 4 + r;
        float ps = acc[r][0] * as0.x + acc[r][1] * as0.y + acc[r][2] * as0.z + acc[r][3] * as0.w
                 + acc[r][4] * as1.x + acc[r][5] * as1.y + acc[r][6] * as1.z + acc[r][7] * as1.w;
        float pd = acc[r][0] * ad0.x + acc[r][1] * ad0.y + acc[r][2] * ad0.z + acc[r][3] * ad0.w
                 + acc[r][4] * ad1.x + acc[r][5] * ad1.y + acc[r][6] * ad1.z + acc[r][7] * ad1.w;
        // reduce over the 8 tx lanes (low 3 bits of lane id) — executed by ALL lanes
#pragma unroll
        for (int o = 1; o < 8; o <<= 1) {
            ps += __shfl_xor_sync(0xffffffffu, ps, o);
            pd += __shfl_xor_sync(0xffffffffu, pd, o);
        }
        if (row < n) {
            *reinterpret_cast<float4*>(&g_h[row * FOUT + tx * 8]) =
                make_float4(acc[r][0], acc[r][1], acc[r][2], acc[r][3]);
            *reinterpret_cast<float4*>(&g_h[row * FOUT + tx * 8 + 4]) =
                make_float4(acc[r][4], acc[r][5], acc[r][6], acc[r][7]);
            if (tx == 0) { g_asrc[row] = ps; g_adst[row] = pd; }
        }
    }
}

// ---------------- kernel 3: per-edge logits + segment max ----------------
__global__ void edge_pass1(const int* __restrict__ ei, int e, int n) {
    int g = blockIdx.x * blockDim.x + threadIdx.x;
    if (g >= e + n) return;
    int src, dst;
    if (g < e) { src = ei[g]; dst = ei[e + g]; }
    else       { src = g - e; dst = src; }          // self-loop
    float v = g_asrc[src] + g_adst[dst];
    v = v > 0.f ? v : 0.2f * v;                     // LeakyReLU(0.2)
    g_e[g] = v;
    atomicMaxFloat(&g_max[dst], v);
}

// ---------------- kernel 4: exp + denom + weighted scatter (16 threads/edge) ----------------
__global__ void edge_pass2(const int* __restrict__ ei, float* __restrict__ out, int e, int n) {
    int t = blockIdx.x * blockDim.x + threadIdx.x;
    int g = t >> 4;
    int l = t & 15;
    if (g >= e + n) return;
    int src, dst;
    if (g < e) { src = ei[g]; dst = ei[e + g]; }
    else       { src = g - e; dst = src; }
    float p = __expf(g_e[g] - g_max[dst]);          // all 16 lanes compute (broadcast loads)
    if (l == 0) atomicAdd(&g_denom[dst], p);
    float4 hv = *reinterpret_cast<const float4*>(&g_h[src * FOUT + l * 4]);
    float* dp = out + (size_t)dst * FOUT + l * 4;
    asm volatile("red.global.add.v4.f32 [%0], {%1, %2, %3, %4};"
                 :: "l"(dp), "f"(p * hv.x), "f"(p * hv.y), "f"(p * hv.z), "f"(p * hv.w)
                 : "memory");
}

// ---------------- kernel 5: normalize + bias ----------------
__global__ void finalize_kernel(float4* __restrict__ out4, const float* __restrict__ bias, int n) {
    int t = blockIdx.x * blockDim.x + threadIdx.x;
    int i = t >> 4;
    int j = t & 15;
    if (i >= n) return;
    float4 v = out4[i * 16 + j];
    float inv = 1.0f / (g_denom[i] + 1e-16f);
    float4 b = reinterpret_cast<const float4*>(bias)[j];
    v.x = v.x * inv + b.x;
    v.y = v.y * inv + b.y;
    v.z = v.z * inv + b.z;
    v.w = v.w * inv + b.w;
    out4[i * 16 + j] = v;
}

// ---------------- launch ----------------
extern "C" void kernel_launch(void* const* d_in, const int* in_sizes, int n_in,
                              void* d_out, int out_size) {
    const float* x       = (const float*)d_in[0];
    const int*   ei      = (const int*)d_in[1];
    const float* W       = (const float*)d_in[2];
    const float* att_src = (const float*)d_in[3];
    const float* att_dst = (const float*)d_in[4];
    const float* bias    = (const float*)d_in[5];
    float* out = (float*)d_out;

    int n = in_sizes[0] / KTOT;   // 100000
    int e = in_sizes[1] / 2;      // 3200000

    int tinit = n * (FOUT / 4);
    init_kernel<<<(tinit + 255) / 256, 256>>>((float4*)out, n);

    gemm_kernel<<<(n + TROWS - 1) / TROWS, 256>>>(x, W, att_src, att_dst, n);

    int te = e + n;
    edge_pass1<<<(te + 255) / 256, 256>>>(ei, e, n);

    long long t2 = (long long)te * 16;
    edge_pass2<<<(int)((t2 + 255) / 256), 256>>>(ei, out, e, n);

    finalize_kernel<<<(n * 16 + 255) / 256, 256>>>((float4*)out, bias, n);
}